// round 15
// baseline (speedup 1.0000x reference)
#include <cuda_runtime.h>
#include <cstdint>

#define KDIM 64
#define MDIM 16
#define TPB  128
#define RPW  64                 // rows per warp (2 per lane)
#define RPB  (4 * RPW)          // 256 rows per block

typedef unsigned long long u64;
typedef unsigned int u32;

__device__ __forceinline__ u64 pack2(float lo, float hi) {
    u64 r;
    asm("mov.b64 %0, {%1, %2};" : "=l"(r) : "f"(lo), "f"(hi));
    return r;
}
__device__ __forceinline__ void unpack2(u64 v, float& lo, float& hi) {
    asm("mov.b64 {%0, %1}, %2;" : "=f"(lo), "=f"(hi) : "l"(v));
}
__device__ __forceinline__ u64 fma2(u64 a, u64 b, u64 c) {
    u64 d;
    asm("fma.rn.f32x2 %0, %1, %2, %3;" : "=l"(d) : "l"(a), "l"(b), "l"(c));
    return d;
}

__global__ __launch_bounds__(TPB, 6)
void dual_compress_kernel(const float* __restrict__ phi_fwd,
                          const float* __restrict__ phi_bwd,
                          const float* __restrict__ alpha_fwd,
                          const float* __restrict__ alpha_bwd,
                          float* __restrict__ out,
                          int V)
{
    // Weight table only: wt[k*4 + q] = m-pairs {2q, 2q+1}; 4 KB total smem.
    __shared__ ulonglong2 wt[KDIM * 4];
    u64* wtf = (u64*)wt;

    const int side = blockIdx.y;
    const float* __restrict__ phi   = side ? phi_bwd   : phi_fwd;
    const float* __restrict__ alpha = side ? alpha_bwd : alpha_fwd;
    float* __restrict__ y = out + (size_t)side * (size_t)V * MDIM;

    const int tid  = threadIdx.x;
    const int w    = tid >> 5;
    const int lane = tid & 31;

    const int wbase = blockIdx.x * RPB + w * RPW;
    const int r0 = wbase + lane;
    const int r1 = wbase + lane + 32;
    const int c0 = min(r0, V - 1);
    const int c1 = min(r1, V - 1);

    // ---- weight table (512 u64 entries / 128 threads = 4 each)
#pragma unroll
    for (int t = 0; t < 4; ++t) {
        int idx = tid + t * TPB;
        int k   = idx >> 3;
        int mp  = idx & 7;
        float w0 = __expf(alpha[(2 * mp)     * KDIM + k]);
        float w1 = __expf(alpha[(2 * mp + 1) * KDIM + k]);
        wtf[idx] = pack2(w0, w1);
    }
    __syncthreads();

    // Direct per-lane row streams: 16 float4 per row.
    const float4* __restrict__ p0 = (const float4*)(phi + (size_t)c0 * KDIM);
    const float4* __restrict__ p1 = (const float4*)(phi + (size_t)c1 * KDIM);

    u64 acc0[8], acc1[8];
#pragma unroll
    for (int q = 0; q < 8; ++q) { acc0[q] = 0ull; acc1[q] = 0ull; }

    // Full unroll: ptxas hoists LDG.128s deep ahead (85-reg budget) for MLP,
    // each 128B line is hit 8x (7 L1 hits after the miss).
#pragma unroll
    for (int j4 = 0; j4 < KDIM / 4; ++j4) {            // 16 quads
        float4 a0 = __ldg(p0 + j4);
        float4 a1 = __ldg(p1 + j4);

        float e0[4], e1[4];
        e0[0] = __expf(a0.x); e0[1] = __expf(a0.y); e0[2] = __expf(a0.z); e0[3] = __expf(a0.w);
        e1[0] = __expf(a1.x); e1[1] = __expf(a1.y); e1[2] = __expf(a1.z); e1[3] = __expf(a1.w);

#pragma unroll
        for (int j = 0; j < 4; ++j) {
            const int k = j4 * 4 + j;
            u64 E0 = pack2(e0[j], e0[j]);
            u64 E1 = pack2(e1[j], e1[j]);
            ulonglong2 w01 = wt[k * 4 + 0];
            ulonglong2 w23 = wt[k * 4 + 1];
            ulonglong2 w45 = wt[k * 4 + 2];
            ulonglong2 w67 = wt[k * 4 + 3];
            acc0[0] = fma2(E0, w01.x, acc0[0]);
            acc1[0] = fma2(E1, w01.x, acc1[0]);
            acc0[1] = fma2(E0, w01.y, acc0[1]);
            acc1[1] = fma2(E1, w01.y, acc1[1]);
            acc0[2] = fma2(E0, w23.x, acc0[2]);
            acc1[2] = fma2(E1, w23.x, acc1[2]);
            acc0[3] = fma2(E0, w23.y, acc0[3]);
            acc1[3] = fma2(E1, w23.y, acc1[3]);
            acc0[4] = fma2(E0, w45.x, acc0[4]);
            acc1[4] = fma2(E1, w45.x, acc1[4]);
            acc0[5] = fma2(E0, w45.y, acc0[5]);
            acc1[5] = fma2(E1, w45.y, acc1[5]);
            acc0[6] = fma2(E0, w67.x, acc0[6]);
            acc1[6] = fma2(E1, w67.x, acc1[6]);
            acc0[7] = fma2(E0, w67.y, acc0[7]);
            acc1[7] = fma2(E1, w67.y, acc1[7]);
        }
    }

    // ---- epilogue: y = log(sum)
    float y0[MDIM], y1[MDIM];
#pragma unroll
    for (int q = 0; q < 8; ++q) {
        float sa, sb;
        unpack2(acc0[q], sa, sb);
        y0[2 * q] = __logf(sa); y0[2 * q + 1] = __logf(sb);
        unpack2(acc1[q], sa, sb);
        y1[2 * q] = __logf(sa); y1[2 * q + 1] = __logf(sb);
    }

    if (r0 < V) {
        float4* o = (float4*)(y + (size_t)r0 * MDIM);
        o[0] = make_float4(y0[0],  y0[1],  y0[2],  y0[3]);
        o[1] = make_float4(y0[4],  y0[5],  y0[6],  y0[7]);
        o[2] = make_float4(y0[8],  y0[9],  y0[10], y0[11]);
        o[3] = make_float4(y0[12], y0[13], y0[14], y0[15]);
    }
    if (r1 < V) {
        float4* o = (float4*)(y + (size_t)r1 * MDIM);
        o[0] = make_float4(y1[0],  y1[1],  y1[2],  y1[3]);
        o[1] = make_float4(y1[4],  y1[5],  y1[6],  y1[7]);
        o[2] = make_float4(y1[8],  y1[9],  y1[10], y1[11]);
        o[3] = make_float4(y1[12], y1[13], y1[14], y1[15]);
    }
}

extern "C" void kernel_launch(void* const* d_in, const int* in_sizes, int n_in,
                              void* d_out, int out_size)
{
    const float* d_out_t   = (const float*)d_in[0];  // (V, 64) fwd phi
    const float* d_in_t    = (const float*)d_in[1];  // (V, 64) bwd phi
    const float* alpha_fwd = (const float*)d_in[2];  // (16, 64)
    const float* alpha_bwd = (const float*)d_in[3];  // (16, 64)
    float* out = (float*)d_out;                      // [y_fwd (V,16) | y_bwd (V,16)]

    const int V = in_sizes[0] / KDIM;

    dim3 grid((V + RPB - 1) / RPB, 2);
    dual_compress_kernel<<<grid, TPB>>>(d_out_t, d_in_t, alpha_fwd, alpha_bwd, out, V);
}

// round 17
// speedup vs baseline: 2.2331x; 2.2331x over previous
#include <cuda_runtime.h>
#include <cuda_fp16.h>
#include <cstdint>

#define KDIM 64
#define MDIM 16
#define TPB  128                 // 4 warps
#define RPW  64                  // rows per warp (2 tiles of 32)
#define RPB  (4 * RPW)           // 256 rows per CTA

typedef unsigned int u32;
typedef unsigned long long u64;

__device__ __forceinline__ u32 sm_u32(const void* p) {
    return (u32)__cvta_generic_to_shared(p);
}
__device__ __forceinline__ u32 sw128(u32 off) {      // SW128 swizzle
    return off ^ ((off >> 3) & 0x70);
}
__device__ __forceinline__ u32 f16x2(float lo, float hi) {
    u32 h;   // first PTX source packs the HIGH half
    asm("cvt.rn.f16x2.f32 %0, %1, %2;" : "=r"(h) : "f"(hi), "f"(lo));
    return h;
}
__device__ __forceinline__ void ldmatrix_x4(u32& a0, u32& a1, u32& a2, u32& a3, u32 addr) {
    asm volatile("ldmatrix.sync.aligned.m8n8.x4.shared.b16 {%0,%1,%2,%3}, [%4];"
                 : "=r"(a0), "=r"(a1), "=r"(a2), "=r"(a3) : "r"(addr));
}
__device__ __forceinline__ void mma16816(float& d0, float& d1, float& d2, float& d3,
                                         u32 a0, u32 a1, u32 a2, u32 a3,
                                         u32 b0, u32 b1) {
    asm volatile(
        "mma.sync.aligned.m16n8k16.row.col.f32.f16.f16.f32 "
        "{%0,%1,%2,%3}, {%4,%5,%6,%7}, {%8,%9}, {%0,%1,%2,%3};"
        : "+f"(d0), "+f"(d1), "+f"(d2), "+f"(d3)
        : "r"(a0), "r"(a1), "r"(a2), "r"(a3), "r"(b0), "r"(b1));
}

__global__ __launch_bounds__(TPB, 6)
void dual_compress_kernel(const float* __restrict__ phi_fwd,
                          const float* __restrict__ phi_bwd,
                          const float* __restrict__ alpha_fwd,
                          const float* __restrict__ alpha_bwd,
                          float* __restrict__ out,
                          int V)
{
    // Warp-private f16 A-tiles (32 rows x 64 halves = 4 KB each): 16 KB total.
    __shared__ __align__(128) __half Atile[4][32 * KDIM];

    const int side = blockIdx.y;
    const float* __restrict__ phi   = side ? phi_bwd   : phi_fwd;
    const float* __restrict__ alpha = side ? alpha_bwd : alpha_fwd;
    float* __restrict__ y = out + (size_t)side * (size_t)V * MDIM;

    const int tid  = threadIdx.x;
    const int w    = tid >> 5;
    const int lane = tid & 31;
    const int l4   = lane >> 2;      // 0..7
    const int l2   = lane & 3;       // 0..3

    const int wbase  = blockIdx.x * RPB + w * RPW;
    const u32 A_base = sm_u32(&Atile[w][0]);

    // ---- B fragments in registers: W = exp(alpha), B[k][n], col-major frags.
    // frag (nt, c): n = nt*8 + l4; k0 = c*16 + 2*l2; regs {k0,k0+1} and {k0+8,k0+9}.
    u32 B[2][4][2];
#pragma unroll
    for (int nt = 0; nt < 2; ++nt) {
        const int n = nt * 8 + l4;
#pragma unroll
        for (int c = 0; c < 4; ++c) {
            const int k0 = c * 16 + 2 * l2;
            float2 lo = *(const float2*)(alpha + n * KDIM + k0);
            float2 hi = *(const float2*)(alpha + n * KDIM + k0 + 8);
            B[nt][c][0] = f16x2(__expf(lo.x), __expf(lo.y));
            B[nt][c][1] = f16x2(__expf(hi.x), __expf(hi.y));
        }
    }

    // ldmatrix lane address components (fixed per lane)
    const int lm_row = lane & 15;    // row within 16-row m-tile
    const int lm_hi  = lane >> 4;    // which 16B k-chunk half

#pragma unroll
    for (int t = 0; t < 2; ++t) {
        const int rbase = wbase + t * 32;

        // ---- fill A-tile: coalesced LDG.128 -> exp -> f16x2 -> swizzled STS.64
#pragma unroll
        for (int i = 0; i < 16; ++i) {
            int idx  = lane + 32 * i;          // 0..511
            int row  = idx >> 4;               // 0..31
            int c4   = idx & 15;               // float4 within row
            int grow = min(rbase + row, V - 1);
            float4 a = __ldg((const float4*)(phi + (size_t)grow * KDIM) + c4);
            u32 h0 = f16x2(__expf(a.x), __expf(a.y));
            u32 h1 = f16x2(__expf(a.z), __expf(a.w));
            u32 off = sw128((u32)(row * 128 + c4 * 8));
            *(uint2*)((char*)&Atile[w][0] + off) = make_uint2(h0, h1);
        }
        __syncwarp();

        // ---- MMA: D[32,16] = A[32,64] * W[16,64]^T
        float D[2][2][4];
#pragma unroll
        for (int mt = 0; mt < 2; ++mt)
#pragma unroll
            for (int nt = 0; nt < 2; ++nt)
#pragma unroll
                for (int q = 0; q < 4; ++q) D[mt][nt][q] = 0.0f;

#pragma unroll
        for (int c = 0; c < 4; ++c) {
#pragma unroll
            for (int mt = 0; mt < 2; ++mt) {
                u32 addr = A_base + sw128((u32)((mt * 16 + lm_row) * 128 +
                                                (c * 2 + lm_hi) * 16));
                u32 a0, a1, a2, a3;
                ldmatrix_x4(a0, a1, a2, a3, addr);
                mma16816(D[mt][0][0], D[mt][0][1], D[mt][0][2], D[mt][0][3],
                         a0, a1, a2, a3, B[0][c][0], B[0][c][1]);
                mma16816(D[mt][1][0], D[mt][1][1], D[mt][1][2], D[mt][1][3],
                         a0, a1, a2, a3, B[1][c][0], B[1][c][1]);
            }
        }
        __syncwarp();   // tile reuse safety for next t

        // ---- epilogue: log + store. Lane holds rows mt*16 + l4 (+8),
        // cols nt*8 + 2*l2 + {0,1}.
#pragma unroll
        for (int mt = 0; mt < 2; ++mt) {
#pragma unroll
            for (int half = 0; half < 2; ++half) {
                const int r = rbase + mt * 16 + half * 8 + l4;
                if (r < V) {
#pragma unroll
                    for (int nt = 0; nt < 2; ++nt) {
                        float v0 = __logf(D[mt][nt][half * 2 + 0]);
                        float v1 = __logf(D[mt][nt][half * 2 + 1]);
                        *(float2*)(y + (size_t)r * MDIM + nt * 8 + 2 * l2) =
                            make_float2(v0, v1);
                    }
                }
            }
        }
    }
}

extern "C" void kernel_launch(void* const* d_in, const int* in_sizes, int n_in,
                              void* d_out, int out_size)
{
    const float* d_out_t   = (const float*)d_in[0];  // (V, 64) fwd phi
    const float* d_in_t    = (const float*)d_in[1];  // (V, 64) bwd phi
    const float* alpha_fwd = (const float*)d_in[2];  // (16, 64)
    const float* alpha_bwd = (const float*)d_in[3];  // (16, 64)
    float* out = (float*)d_out;                      // [y_fwd (V,16) | y_bwd (V,16)]

    const int V = in_sizes[0] / KDIM;

    dim3 grid((V + RPB - 1) / RPB, 2);
    dual_compress_kernel<<<grid, TPB>>>(d_out_t, d_in_t, alpha_fwd, alpha_bwd, out, V);
}